// round 12
// baseline (speedup 1.0000x reference)
#include <cuda_runtime.h>
#include <cuda_fp16.h>
#include <math.h>
#include <stdint.h>

#define NNODE 1000
#define NPAD  1024
#define BATCH 32
#define SEQ   48
#define HID   64
#define FEATD 40
#define XCOLS (SEQ*BATCH*FEATD)   // 61440
#define HCOLS (BATCH*HID)         // 2048
#define GP    120

// ---------------- static device scratch ----------------
__device__ float g_dis[NPAD];
__device__ __align__(128) __half g_L16[NPAD*NPAD];
__device__ __align__(128) __half g_x16 [(size_t)NPAD*XCOLS];  // fp16 x, [node][col]
__device__ __align__(128) float  g_LxT [(size_t)NPAD*XCOLS];
__device__ __align__(128) float  g_hT  [NPAD*HCOLS];
__device__ __align__(128) __half g_h16 [NPAD*HCOLS];          // fp16 h, [node][col]
__device__ __align__(128) __half g_rh16[NPAD*HCOLS];          // fp16 r*h
__device__ __align__(128) float  g_uT  [NPAD*HCOLS];
__device__ __align__(128) float  g_LhT [NPAD*HCOLS];
__device__ __align__(128) float  g_LrhT[NPAD*HCOLS];
__device__ __align__(128) __half g_W1_16[128*112];  // zero-init covers k=104..111 pad
__device__ __align__(128) __half g_W2_16[64*112];

__device__ __forceinline__ uint32_t packh(float a, float b) {
    __half2 t = __floats2half2_rn(a, b);
    return *reinterpret_cast<uint32_t*>(&t);
}
__device__ __forceinline__ uint32_t smem_u32(const void* p) {
    uint32_t a;
    asm("{ .reg .u64 t; cvta.to.shared.u64 t, %1; cvt.u32.u64 %0, t; }" : "=r"(a) : "l"(p));
    return a;
}

// ---------------- prep ----------------
__global__ void k_zero_state() {
    int i = blockIdx.x * blockDim.x + threadIdx.x;
    if (i < NPAD * HCOLS) {
        g_hT[i] = 0.f;
        g_h16[i] = __float2half(0.f);
        g_rh16[i] = __float2half(0.f);   // pad rows stay 0 forever; real rows rewritten each step
    }
}
__global__ void k_zero_xpad() {
    size_t i = (size_t)blockIdx.x * blockDim.x + threadIdx.x;
    size_t tot = (size_t)(NPAD - NNODE) * XCOLS;
    if (i < tot) g_x16[(size_t)NNODE * XCOLS + i] = __float2half(0.f);
}
__global__ void k_rowsum(const float* __restrict__ adj) {
    int m = blockIdx.x, tid = threadIdx.x;
    float s = 0.f;
    for (int k = tid; k < NNODE; k += 256) s += adj[m * NNODE + k];
    __shared__ float sm[256];
    sm[tid] = s; __syncthreads();
    for (int st = 128; st > 0; st >>= 1) { if (tid < st) sm[tid] += sm[tid + st]; __syncthreads(); }
    if (tid == 0) g_dis[m] = rsqrtf(sm[0] + 1.0f);
}
__global__ void k_buildL(const float* __restrict__ adj) {
    int i = blockIdx.x * blockDim.x + threadIdx.x;
    if (i >= NPAD * NPAD) return;
    int m = i >> 10, n = i & (NPAD - 1);
    float v = 0.f;
    if (m < NNODE && n < NNODE)
        v = g_dis[m] * (adj[m * NNODE + n] + (m == n ? 1.f : 0.f)) * g_dis[n];
    g_L16[i] = __float2half(v);
}
__global__ void k_prepW(const float* __restrict__ W1, const float* __restrict__ W2) {
    int i = blockIdx.x * blockDim.x + threadIdx.x;
    if (i < 104 * 128) {
        int k = i >> 7, o = i & 127;
        g_W1_16[o * 112 + k] = __float2half(W1[i]);
    } else if (i < 104 * 128 + 104 * 64) {
        int j = i - 104 * 128;
        int k = j >> 6, o = j & 63;
        g_W2_16[o * 112 + k] = __float2half(W2[j]);
    }
}
__global__ void k_aspect(const float* __restrict__ inp,
                         const float* __restrict__ Wo, const float* __restrict__ bo,
                         const float* __restrict__ Wd, const float* __restrict__ bd,
                         const float* __restrict__ We, const float* __restrict__ be,
                         const float* __restrict__ Wi, const float* __restrict__ bi) {
    size_t i = (size_t)blockIdx.x * blockDim.x + threadIdx.x;
    if (i >= (size_t)NNODE * XCOLS) return;
    int n = (int)(i / XCOLS);
    int col = (int)(i - (size_t)n * XCOLS);
    int s = col / (BATCH * FEATD);
    int rem = col - s * (BATCH * FEATD);
    int b = rem / FEATD, f = rem - b * FEATD;
    const float* base = inp + (((size_t)(b * SEQ + s) * NNODE + n) * 21);
    int fo = f % 10;
    float acc;
    if (f < 10) {
        const int idx[5] = {2, 5, 8, 9, 12};
        acc = __ldg(bo + fo);
        #pragma unroll
        for (int j = 0; j < 5; j++) acc += __ldg(base + idx[j]) * __ldg(Wo + j * 10 + fo);
    } else if (f < 20) {
        const int idx[3] = {10, 14, 15};
        acc = __ldg(bd + fo);
        #pragma unroll
        for (int j = 0; j < 3; j++) acc += __ldg(base + idx[j]) * __ldg(Wd + j * 10 + fo);
    } else if (f < 30) {
        const int idx[2] = {13, 17};
        acc = __ldg(be + fo);
        #pragma unroll
        for (int j = 0; j < 2; j++) acc += __ldg(base + idx[j]) * __ldg(We + j * 10 + fo);
    } else {
        const int idx[2] = {19, 20};
        acc = __ldg(bi + fo);
        #pragma unroll
        for (int j = 0; j < 2; j++) acc += __ldg(base + idx[j]) * __ldg(Wi + j * 10 + fo);
    }
    g_x16[(size_t)n * XCOLS + col] = __float2half(acc);
}

// ---------------- mma16816 fp16 ----------------
__device__ __forceinline__ void mma16816(float* d, const uint32_t* a, const uint32_t* b) {
    asm volatile(
        "mma.sync.aligned.m16n8k16.row.col.f32.f16.f16.f32 "
        "{%0,%1,%2,%3}, {%4,%5,%6,%7}, {%8,%9}, {%0,%1,%2,%3};"
        : "+f"(d[0]), "+f"(d[1]), "+f"(d[2]), "+f"(d[3])
        : "r"(a[0]), "r"(a[1]), "r"(a[2]), "r"(a[3]), "r"(b[0]), "r"(b[1]));
}

// ---------------- GEMM: C = A@B; A fp16 K-major, B fp16 [k][n] ----------------
// cp.async double-buffered A, register-prefetched B (u16, repacked), ONE sync per chunk.
// smem (halves): buffer stride 10240; A@0 (128x40), B@5120 (128x40).
__device__ __forceinline__ void cpa_chunkH(uint32_t smb, int p, const __half* A,
                                           int m0, int k0, int tid) {
    #pragma unroll
    for (int it = 0; it < 2; it++) {
        int i = it * 256 + tid;
        int r = i >> 2, s = i & 3;
        const __half* src = A + (size_t)(m0 + r) * NPAD + k0 + s * 8;
        uint32_t dst = smb + p * 20480 + r * 80 + s * 16;
        asm volatile("cp.async.cg.shared.global [%0], [%1], 16;" :: "r"(dst), "l"(src));
    }
}
__device__ __forceinline__ void storeBH(__half* sm, int p, const unsigned short* pb, int bn, int bk4) {
    uint32_t w[8];
    #pragma unroll
    for (int j = 0; j < 8; j++)
        w[j] = (uint32_t)pb[2 * j] | ((uint32_t)pb[2 * j + 1] << 16);
    __half* b = sm + p * 10240 + 5120 + bn * 40 + bk4;
    *(uint4*)b       = make_uint4(w[0], w[1], w[2], w[3]);
    *(uint4*)(b + 8) = make_uint4(w[4], w[5], w[6], w[7]);
}
__global__ __launch_bounds__(256)
void mma_gemmH(const __half* __restrict__ A, const __half* __restrict__ B,
               float* __restrict__ C, int ldc) {
    extern __shared__ __half sm[];
    uint32_t smb = smem_u32(sm);
    int tid = threadIdx.x, wid = tid >> 5, lane = tid & 31;
    int m0 = blockIdx.y * 128, n0 = blockIdx.x * 128;
    int wm = (wid & 1) * 64, wn = (wid >> 1) * 32;
    int qr = lane >> 2, qc = lane & 3;
    int bn = tid & 127, bk4 = (tid >> 7) * 16;
    const unsigned short* Bp = (const unsigned short*)(B + n0 + bn);
    float acc[4][4][4];
    #pragma unroll
    for (int a = 0; a < 4; a++)
        #pragma unroll
        for (int b = 0; b < 4; b++)
            #pragma unroll
            for (int c = 0; c < 4; c++) acc[a][b][c] = 0.f;
    unsigned short pb[16];

    // prologue: A(0) via cp.async; B(0) stored; B(1) in regs
    cpa_chunkH(smb, 0, A, m0, 0, tid);
    asm volatile("cp.async.commit_group;" ::: "memory");
    #pragma unroll
    for (int j = 0; j < 16; j++) pb[j] = Bp[(size_t)(bk4 + j) * ldc];
    storeBH(sm, 0, pb, bn, bk4);
    #pragma unroll
    for (int j = 0; j < 16; j++) pb[j] = Bp[(size_t)(32 + bk4 + j) * ldc];
    asm volatile("cp.async.wait_group 0;" ::: "memory");
    __syncthreads();

    for (int c = 0; c < 32; c++) {
        int p = c & 1;
        if (c < 31) {
            cpa_chunkH(smb, p ^ 1, A, m0, (c + 1) * 32, tid);
            storeBH(sm, p ^ 1, pb, bn, bk4);
        }
        asm volatile("cp.async.commit_group;" ::: "memory");
        if (c < 30) {
            int k0 = (c + 2) * 32;
            #pragma unroll
            for (int j = 0; j < 16; j++) pb[j] = Bp[(size_t)(k0 + bk4 + j) * ldc];
        }
        const __half* sA = sm + p * 10240;
        const __half* sB = sA + 5120;
        #pragma unroll
        for (int ks = 0; ks < 32; ks += 16) {
            uint32_t ah[4][4], bh[4][2];
            #pragma unroll
            for (int mi = 0; mi < 4; mi++) {
                int r = wm + mi * 16 + qr;
                ah[mi][0] = *(const uint32_t*)(sA + r * 40 + ks + qc * 2);
                ah[mi][1] = *(const uint32_t*)(sA + (r + 8) * 40 + ks + qc * 2);
                ah[mi][2] = *(const uint32_t*)(sA + r * 40 + ks + 8 + qc * 2);
                ah[mi][3] = *(const uint32_t*)(sA + (r + 8) * 40 + ks + 8 + qc * 2);
            }
            #pragma unroll
            for (int ni = 0; ni < 4; ni++) {
                int r = wn + ni * 8 + qr;
                bh[ni][0] = *(const uint32_t*)(sB + r * 40 + ks + qc * 2);
                bh[ni][1] = *(const uint32_t*)(sB + r * 40 + ks + 8 + qc * 2);
            }
            #pragma unroll
            for (int mi = 0; mi < 4; mi++)
                #pragma unroll
                for (int ni = 0; ni < 4; ni++) mma16816(acc[mi][ni], ah[mi], bh[ni]);
        }
        asm volatile("cp.async.wait_group 0;" ::: "memory");
        __syncthreads();
    }
    #pragma unroll
    for (int mi = 0; mi < 4; mi++) {
        int r = m0 + wm + mi * 16 + qr;
        #pragma unroll
        for (int ni = 0; ni < 4; ni++) {
            int cc = n0 + wn + ni * 8 + qc * 2;
            *(float2*)(C + (size_t)r * ldc + cc)       = make_float2(acc[mi][ni][0], acc[mi][ni][1]);
            *(float2*)(C + (size_t)(r + 8) * ldc + cc) = make_float2(acc[mi][ni][2], acc[mi][ni][3]);
        }
    }
}

// ---------------- gate GEMM: rows n*32+b, K=[Lx(40)|Lh(64)|pad8], N=128; sigmoid + chunk remap ----------------
__global__ __launch_bounds__(256)
void k_gateG(const float* __restrict__ b1, int t) {
    extern __shared__ char dyn[];
    __half* sA = (__half*)dyn;
    __half* sW = sA + 128 * GP;
    float* sb = (float*)(sW + 128 * GP);
    int tid = threadIdx.x, wid = tid >> 5, lane = tid & 31;
    int n0 = blockIdx.x * 4;
    for (int g = tid; g < 512; g += 256) {   // zero A pad k=104..111
        int r = g >> 2, k = 104 + (g & 3) * 2;
        *(uint32_t*)(sA + r * GP + k) = 0;
    }
    for (int g = tid; g < 2560; g += 256) {  // Lx (fp32 L@x)
        int ni = g / 640, rem = (g - ni * 640) * 2;
        float2 v = *(const float2*)(g_LxT + (size_t)(n0 + ni) * XCOLS + (size_t)t * 1280 + rem);
        int b = rem / 40, k = rem - b * 40;
        *(uint32_t*)(sA + (ni * 32 + b) * GP + k) = packh(v.x, v.y);
    }
    for (int g = tid; g < 4096; g += 256) {  // Lh
        int ni = g >> 10, rem = (g & 1023) * 2;
        float2 v = *(const float2*)(g_LhT + (n0 + ni) * HCOLS + rem);
        int row = ni * 32 + (rem >> 6), k = 40 + (rem & 63);
        *(uint32_t*)(sA + row * GP + k) = packh(v.x, v.y);
    }
    for (int g = tid; g < 1792; g += 256) {  // W (pre-split fp16, uint4)
        int o = g / 14, j = g - o * 14;
        uint4 v = *(const uint4*)(g_W1_16 + o * 112 + j * 8);
        *(uint4*)(sW + o * GP + j * 8) = v;
    }
    if (tid < 128) sb[tid] = b1[tid];
    __syncthreads();

    int wm = (wid & 1) * 64, wn = (wid >> 1) * 32;
    int qr = lane >> 2, qc = lane & 3;
    float acc[4][4][4];
    #pragma unroll
    for (int a = 0; a < 4; a++)
        #pragma unroll
        for (int b = 0; b < 4; b++)
            #pragma unroll
            for (int c = 0; c < 4; c++) acc[a][b][c] = 0.f;
    for (int ks = 0; ks < 112; ks += 16) {
        uint32_t ah[4][4], bh[4][2];
        #pragma unroll
        for (int mi = 0; mi < 4; mi++) {
            int r = wm + mi * 16 + qr;
            ah[mi][0] = *(const uint32_t*)(sA + r * GP + ks + qc * 2);
            ah[mi][1] = *(const uint32_t*)(sA + (r + 8) * GP + ks + qc * 2);
            ah[mi][2] = *(const uint32_t*)(sA + r * GP + ks + 8 + qc * 2);
            ah[mi][3] = *(const uint32_t*)(sA + (r + 8) * GP + ks + 8 + qc * 2);
        }
        #pragma unroll
        for (int ni = 0; ni < 4; ni++) {
            int r = wn + ni * 8 + qr;
            bh[ni][0] = *(const uint32_t*)(sW + r * GP + ks + qc * 2);
            bh[ni][1] = *(const uint32_t*)(sW + r * GP + ks + 8 + qc * 2);
        }
        #pragma unroll
        for (int mi = 0; mi < 4; mi++)
            #pragma unroll
            for (int ni = 0; ni < 4; ni++) mma16816(acc[mi][ni], ah[mi], bh[ni]);
    }
    #pragma unroll
    for (int mi = 0; mi < 4; mi++) {
        #pragma unroll
        for (int ni = 0; ni < 4; ni++) {
            int o = wn + ni * 8 + qc * 2;
            int half_ = o >> 6, ch = o & 63;
            #pragma unroll
            for (int hr = 0; hr < 2; hr++) {
                int row = wm + mi * 16 + qr + hr * 8;
                int n = n0 + (row >> 5), b = row & 31;
                float s0 = 1.f / (1.f + expf(-(acc[mi][ni][hr * 2]     + sb[o])));
                float s1 = 1.f / (1.f + expf(-(acc[mi][ni][hr * 2 + 1] + sb[o + 1])));
                if (n < 500) {
                    int idx = (2 * n + half_) * HCOLS + b * 64 + ch;
                    float2 h2 = *(float2*)(g_hT + idx);
                    *(uint32_t*)(g_rh16 + idx) = packh(h2.x * s0, h2.y * s1);
                } else {
                    int idx = (2 * (n - 500) + half_) * HCOLS + b * 64 + ch;
                    *(float2*)(g_uT + idx) = make_float2(s0, s1);
                }
            }
        }
    }
}

// ---------------- cand GEMM: K=[Lx|Lrh], N=64; tanh + GRU update ----------------
__global__ __launch_bounds__(256)
void k_candG(const float* __restrict__ b2, int t) {
    extern __shared__ char dyn[];
    __half* sA = (__half*)dyn;
    __half* sW = sA + 128 * GP;
    float* sb = (float*)(sW + 64 * GP);
    int tid = threadIdx.x, wid = tid >> 5, lane = tid & 31;
    int n0 = blockIdx.x * 4;
    for (int g = tid; g < 512; g += 256) {
        int r = g >> 2, k = 104 + (g & 3) * 2;
        *(uint32_t*)(sA + r * GP + k) = 0;
    }
    for (int g = tid; g < 2560; g += 256) {
        int ni = g / 640, rem = (g - ni * 640) * 2;
        float2 v = *(const float2*)(g_LxT + (size_t)(n0 + ni) * XCOLS + (size_t)t * 1280 + rem);
        int b = rem / 40, k = rem - b * 40;
        *(uint32_t*)(sA + (ni * 32 + b) * GP + k) = packh(v.x, v.y);
    }
    for (int g = tid; g < 4096; g += 256) {
        int ni = g >> 10, rem = (g & 1023) * 2;
        float2 v = *(const float2*)(g_LrhT + (n0 + ni) * HCOLS + rem);
        int row = ni * 32 + (rem >> 6), k = 40 + (rem & 63);
        *(uint32_t*)(sA + row * GP + k) = packh(v.x, v.y);
    }
    for (int g = tid; g < 896; g += 256) {
        int o = g / 14, j = g - o * 14;
        uint4 v = *(const uint4*)(g_W2_16 + o * 112 + j * 8);
        *(uint4*)(sW + o * GP + j * 8) = v;
    }
    if (tid < 64) sb[tid] = b2[tid];
    __syncthreads();

    int wm = (wid & 3) * 32, wn = (wid >> 2) * 32;
    int qr = lane >> 2, qc = lane & 3;
    float acc[2][4][4];
    #pragma unroll
    for (int a = 0; a < 2; a++)
        #pragma unroll
        for (int b = 0; b < 4; b++)
            #pragma unroll
            for (int c = 0; c < 4; c++) acc[a][b][c] = 0.f;
    for (int ks = 0; ks < 112; ks += 16) {
        uint32_t ah[2][4], bh[4][2];
        #pragma unroll
        for (int mi = 0; mi < 2; mi++) {
            int r = wm + mi * 16 + qr;
            ah[mi][0] = *(const uint32_t*)(sA + r * GP + ks + qc * 2);
            ah[mi][1] = *(const uint32_t*)(sA + (r + 8) * GP + ks + qc * 2);
            ah[mi][2] = *(const uint32_t*)(sA + r * GP + ks + 8 + qc * 2);
            ah[mi][3] = *(const uint32_t*)(sA + (r + 8) * GP + ks + 8 + qc * 2);
        }
        #pragma unroll
        for (int ni = 0; ni < 4; ni++) {
            int r = wn + ni * 8 + qr;
            bh[ni][0] = *(const uint32_t*)(sW + r * GP + ks + qc * 2);
            bh[ni][1] = *(const uint32_t*)(sW + r * GP + ks + 8 + qc * 2);
        }
        #pragma unroll
        for (int mi = 0; mi < 2; mi++)
            #pragma unroll
            for (int ni = 0; ni < 4; ni++) mma16816(acc[mi][ni], ah[mi], bh[ni]);
    }
    #pragma unroll
    for (int mi = 0; mi < 2; mi++) {
        #pragma unroll
        for (int ni = 0; ni < 4; ni++) {
            int o = wn + ni * 8 + qc * 2;
            #pragma unroll
            for (int hr = 0; hr < 2; hr++) {
                int row = wm + mi * 16 + qr + hr * 8;
                int n = n0 + (row >> 5), b = row & 31;
                float c0 = tanhf(acc[mi][ni][hr * 2]     + sb[o]);
                float c1 = tanhf(acc[mi][ni][hr * 2 + 1] + sb[o + 1]);
                int idx = n * HCOLS + b * 64 + o;
                float2 u2 = *(float2*)(g_uT + idx);
                float2 h2 = *(float2*)(g_hT + idx);
                float hn0 = u2.x * h2.x + (1.f - u2.x) * c0;
                float hn1 = u2.y * h2.y + (1.f - u2.y) * c1;
                *(float2*)(g_hT + idx) = make_float2(hn0, hn1);
                *(uint32_t*)(g_h16 + idx) = packh(hn0, hn1);
            }
        }
    }
}

__global__ void k_out(float* __restrict__ out) {
    int i = blockIdx.x * blockDim.x + threadIdx.x;
    if (i >= BATCH * NNODE * HID) return;
    int ch = i & (HID - 1);
    int n  = (i >> 6) % NNODE;
    int b  = i / (NNODE * HID);
    out[i] = g_hT[n * HCOLS + b * HID + ch];
}

// ---------------- launcher ----------------
extern "C" void kernel_launch(void* const* d_in, const int* in_sizes, int n_in,
                              void* d_out, int out_size) {
    const float* inp = (const float*)d_in[0];
    const float* adj = (const float*)d_in[1];
    const float* Wo = (const float*)d_in[2];  const float* bo = (const float*)d_in[3];
    const float* Wd = (const float*)d_in[4];  const float* bd = (const float*)d_in[5];
    const float* We = (const float*)d_in[6];  const float* be = (const float*)d_in[7];
    const float* Wi = (const float*)d_in[8];  const float* bi = (const float*)d_in[9];
    const float* W1 = (const float*)d_in[10]; const float* b1 = (const float*)d_in[11];
    const float* W2 = (const float*)d_in[12]; const float* b2 = (const float*)d_in[13];
    float* out = (float*)d_out;

    const int GEMM_SMEM = 2 * 20480;                          // 40960
    const int GATE_SMEM = 2 * 128 * GP * 2 + 128 * 4;         // 61952
    const int CAND_SMEM = (128 + 64) * GP * 2 + 64 * 4;       // 46336
    cudaFuncSetAttribute(mma_gemmH, cudaFuncAttributeMaxDynamicSharedMemorySize, GEMM_SMEM);
    cudaFuncSetAttribute(k_gateG, cudaFuncAttributeMaxDynamicSharedMemorySize, GATE_SMEM);
    cudaFuncSetAttribute(k_candG, cudaFuncAttributeMaxDynamicSharedMemorySize, CAND_SMEM);

    __half *L16, *x16, *h16, *rh16;
    float *LxT, *LhT, *LrhT;
    cudaGetSymbolAddress((void**)&L16, g_L16);
    cudaGetSymbolAddress((void**)&x16, g_x16);   cudaGetSymbolAddress((void**)&LxT, g_LxT);
    cudaGetSymbolAddress((void**)&h16, g_h16);   cudaGetSymbolAddress((void**)&rh16, g_rh16);
    cudaGetSymbolAddress((void**)&LhT, g_LhT);   cudaGetSymbolAddress((void**)&LrhT, g_LrhT);

    k_zero_state<<<(NPAD * HCOLS + 255) / 256, 256>>>();
    k_zero_xpad<<<(int)(((size_t)(NPAD - NNODE) * XCOLS + 255) / 256), 256>>>();
    k_rowsum<<<NNODE, 256>>>(adj);
    k_buildL<<<(NPAD * NPAD) / 256, 256>>>(adj);
    k_prepW<<<78, 256>>>(W1, W2);
    k_aspect<<<(int)(((size_t)NNODE * XCOLS + 255) / 256), 256>>>(inp, Wo, bo, Wd, bd, We, be, Wi, bi);

    mma_gemmH<<<dim3(XCOLS / 128, NPAD / 128), 256, GEMM_SMEM>>>(L16, x16, LxT, XCOLS);

    for (int t = 0; t < SEQ; ++t) {
        mma_gemmH<<<dim3(HCOLS / 128, NPAD / 128), 256, GEMM_SMEM>>>(L16, h16, LhT, HCOLS);
        k_gateG<<<250, 256, GATE_SMEM>>>(b1, t);
        mma_gemmH<<<dim3(HCOLS / 128, NPAD / 128), 256, GEMM_SMEM>>>(L16, rh16, LrhT, HCOLS);
        k_candG<<<250, 256, CAND_SMEM>>>(b2, t);
    }

    k_out<<<(BATCH * NNODE * HID + 255) / 256, 256>>>(out);
}